// round 16
// baseline (speedup 1.0000x reference)
#include <cuda_runtime.h>
#include <cuda_bf16.h>
#include <math.h>

// Problem constants
#define NB   64
#define NT   512
#define NEMB 128
#define NHID 256
#define NMEL 80
#define NVOC 256
#define G4   1024      // 4*NHID
#define LMAX 1536      // safe upper bound on expanded length (measured L=626)

typedef unsigned long long ull;

// ---------------- device scratch (static: no allocations allowed) ----------------
__device__ int   g_tok[NB * LMAX];                    // expanded token ids (NVOC == padding row)
__device__ float g_tab[2 * 257 * G4];                 // [dir][vocab(+pad)][gate-row] input proj + biases
__device__ float g_h[2ull * LMAX * NHID * NB];        // [dir][l][u][b] hidden states (batch innermost)

// ---------------- packed f32x2 + cluster helpers ----------------
__device__ __forceinline__ ull pack2(float lo, float hi) {
    ull r; asm("mov.b64 %0, {%1, %2};" : "=l"(r) : "f"(lo), "f"(hi)); return r;
}
__device__ __forceinline__ float2 unpack2(ull v) {
    float2 r; asm("mov.b64 {%0, %1}, %2;" : "=f"(r.x), "=f"(r.y) : "l"(v)); return r;
}
__device__ __forceinline__ void ffma2(ull& d, ull a, ull b) {
    asm("fma.rn.f32x2 %0, %1, %2, %0;" : "+l"(d) : "l"(a), "l"(b));
}
__device__ __forceinline__ void add2(ull& d, ull a) {
    asm("add.rn.f32x2 %0, %0, %1;" : "+l"(d) : "l"(a));
}
__device__ __forceinline__ unsigned smem_u32(const void* p) {
    unsigned a;
    asm("{ .reg .u64 t; cvta.to.shared.u64 t, %1; cvt.u32.u64 %0, t; }" : "=r"(a) : "l"(p));
    return a;
}
__device__ __forceinline__ unsigned mapa_rank(unsigned smem_addr, int rank) {
    unsigned r;
    asm("mapa.shared::cluster.u32 %0, %1, %2;" : "=r"(r) : "r"(smem_addr), "r"(rank));
    return r;
}
__device__ __forceinline__ void st_cluster_u64(unsigned addr, ull v) {
    asm volatile("st.shared::cluster.u64 [%0], %1;" :: "r"(addr), "l"(v) : "memory");
}

// ---------------- K1: input-projection tables (embed @ wih.T + bih + bhh) ----------------
__global__ void k_tab(const float* __restrict__ embed,
                      const float* __restrict__ wih_f, const float* __restrict__ bih_f,
                      const float* __restrict__ bhh_f,
                      const float* __restrict__ wih_b, const float* __restrict__ bih_b,
                      const float* __restrict__ bhh_b) {
    int bid = blockIdx.x;          // 514 blocks: dir*257 + v
    int dir = bid / 257;
    int v   = bid % 257;
    const float* wih = dir ? wih_b : wih_f;
    const float* bih = dir ? bih_b : bih_f;
    const float* bhh = dir ? bhh_b : bhh_f;
    for (int r = threadIdx.x; r < G4; r += 256) {
        float a = bih[r] + bhh[r];
        if (v < NVOC) {
            const float* w = wih + r * NEMB;
            const float* e = embed + v * NEMB;
            #pragma unroll 8
            for (int k = 0; k < NEMB; k++) a += e[k] * w[k];
        }
        g_tab[dir * (257 * G4) + v * G4 + r] = a;
    }
}

// ---------------- K2: durations, cumsum, length-regulator expand ----------------
__global__ void k_expand(const int* __restrict__ x,
                         const float* __restrict__ embed,
                         const float* __restrict__ dp_w,
                         const float* __restrict__ dp_b, int L) {
    __shared__ int s_cum[NT];
    int b = blockIdx.x;
    int t = threadIdx.x;          // 512 threads
    int xv = x[b * NT + t];
    float d = dp_b[0];
    const float* e = embed + xv * NEMB;
    #pragma unroll 8
    for (int k = 0; k < NEMB; k++) d += e[k] * dp_w[k];
    d = fmaxf(d, 0.f);
    int dur = (int)floorf(d) + 1;
    s_cum[t] = dur;
    __syncthreads();
    if (t == 0) {                 // tiny sequential scan (512 ints)
        int acc = 0;
        for (int i = 0; i < NT; i++) { acc += s_cum[i]; s_cum[i] = acc; }
    }
    __syncthreads();
    int end   = s_cum[t];
    int start = (t == 0) ? 0 : s_cum[t - 1];
    for (int p = start; p < end && p < L; p++) g_tok[b * LMAX + p] = xv;
    int len = s_cum[NT - 1];
    for (int p = len + t; p < L; p += NT) g_tok[b * LMAX + p] = NVOC;  // padding row
}

// ---------------- K3: cluster-decomposed persistent bidirectional LSTM ----------------
// Cluster of 8 CTAs = one (dir, 8-sequence) group. Rank r owns units [r*32, r*32+32).
// h exchange = DSMEM all-to-all push + one HW cluster barrier per step. NO L2 flags.
__device__ __forceinline__ float sigm(float x)   { return __fdividef(1.f, 1.f + __expf(-x)); }
__device__ __forceinline__ float tanh_f(float x) { return 1.f - __fdividef(2.f, __expf(2.f * x) + 1.f); }

// 128KB weights + 32KB double-buffered dup h + 12KB k-split reduction = 172KB
#define LSTM_SMEM (256 * 128 * 4 + 2 * 256 * 8 * 8 + 384 * 4 * 8)

__global__ void __launch_bounds__(512, 1) __cluster_dims__(8, 1, 1)
k_lstm(const float* __restrict__ whh_f, const float* __restrict__ whh_b, int L) {
    extern __shared__ float sm[];
    float* w_smf = sm;                       // [k=256][col=128], col = ul*4 + gate
    ull*   h2    = (ull*)(sm + 256 * 128);   // [buf=2][k=256][seq=8] duplicated (h,h)
    ull*   red   = h2 + 2 * 256 * 8;         // [3][128][4] k-split partial gate sums

    int bx  = blockIdx.x;          // 128 blocks = 16 clusters x 8 ranks (all resident)
    int dir = bx >> 6;             // 0 fwd, 1 bwd
    int g   = (bx >> 3) & 7;       // sequence group (8 batches)
    int r   = bx & 7;              // cluster rank = unit slice
    int u0  = r * 32;
    int tid = threadIdx.x;         // 512 threads, 16 warps
    int kq  = tid >> 7;            // k-quarter 0..3 (64 k each); warp = kq*4 + uhi
    int uhi = (tid >> 5) & 3;
    int lane = tid & 31;
    int ulo = lane >> 2;           // 0..7
    int sp  = lane & 3;            // seq pair: local seqs 2sp, 2sp+1
    int ul  = uhi * 8 + ulo;       // 0..31
    int urow = u0 + ul;            // global unit

    const float* whh = dir ? whh_b : whh_f;
    // Load this rank's whh slice k-major: w_smf[k*128 + u*4 + gg] = whh[(gg*NHID+u0+u)*NHID + k]
    for (int i = tid; i < 128 * 256; i += 512) {
        int col = i & 127, k = i >> 7;
        int u = col >> 2, gg = col & 3;
        w_smf[k * 128 + col] = whh[(gg * NHID + u0 + u) * NHID + k];
    }
    __syncthreads();   // own-block weights ready (peers don't read our weights)

    const ulonglong2* wp = (const ulonglong2*)w_smf + kq * 64 * 32 + ul;   // + k*32
    const float* tabd  = g_tab + dir * (257 * G4);
    float* hout_base   = g_h + (size_t)dir * LMAX * NHID * NB;             // [l][u][b]

    int bg0 = g * 8 + 2 * sp;      // global batch of first cell
    int rix = (tid & 127) * 4;     // reduction slot (x4 u64)
    unsigned h2_u32 = smem_u32(h2);
    unsigned rank_base[8];
    #pragma unroll
    for (int rk = 0; rk < 8; rk++) rank_base[rk] = mapa_rank(h2_u32, rk);
    unsigned my_off = (unsigned)(urow * 8 + 2 * sp) * 8u;   // byte offset within a buffer

    float c0 = 0.f, c1 = 0.f;
    // prefetch s=0 biases (kq0 only; others keep 0)
    ull pf_if0 = 0, pf_go0 = 0, pf_if1 = 0, pf_go1 = 0;
    if (kq == 0) {
        int l0 = dir ? (L - 1) : 0;
        int tok0 = g_tok[bg0 * LMAX + l0];
        int tok1 = g_tok[(bg0 + 1) * LMAX + l0];
        const float* tr0 = tabd + tok0 * G4 + urow;
        const float* tr1 = tabd + tok1 * G4 + urow;
        pf_if0 = pack2(tr0[0], tr0[NHID]); pf_go0 = pack2(tr0[2 * NHID], tr0[3 * NHID]);
        pf_if1 = pack2(tr1[0], tr1[NHID]); pf_go1 = pack2(tr1[2 * NHID], tr1[3 * NHID]);
    }

    for (int s = 0; s < L; s++) {
        int l = dir ? (L - 1 - s) : s;
        ull aif0 = pf_if0, ago0 = pf_go0, aif1 = pf_if1, ago1 = pf_go1;

        if (s > 0) {
            int rb = (s & 1) ^ 1;  // h(s-1) buffer
            const ulonglong2* hp = (const ulonglong2*)(h2 + rb * 2048) + kq * 64 * 4 + sp; // + k*4
            // gates += h @ whh.T over this warp's k-quarter (2 cells x 2 packed gate-pairs)
            #pragma unroll 8
            for (int k = 0; k < 64; k++) {
                ulonglong2 w = wp[k * 32];
                ulonglong2 h = hp[k * 4];
                ffma2(aif0, w.x, h.x);
                ffma2(ago0, w.y, h.x);
                ffma2(aif1, w.x, h.y);
                ffma2(ago1, w.y, h.y);
            }
            // k-split reduction: quarters 1..3 publish, quarter 0 accumulates
            if (kq) {
                ulonglong2* r2 = (ulonglong2*)(red + (kq - 1) * 512 + rix);
                r2[0] = make_ulonglong2(aif0, ago0);
                r2[1] = make_ulonglong2(aif1, ago1);
            }
            __syncthreads();
            if (!kq) {
                #pragma unroll
                for (int q = 0; q < 3; q++) {
                    const ulonglong2* r2 = (const ulonglong2*)(red + q * 512 + rix);
                    ulonglong2 p0 = r2[0], p1 = r2[1];
                    add2(aif0, p0.x); add2(ago0, p0.y);
                    add2(aif1, p1.x); add2(ago1, p1.y);
                }
            }
        }

        float h0 = 0.f, h1 = 0.f;
        if (!kq) {
            // LSTM cells (PyTorch gate order i,f,g,o)
            float2 vif0 = unpack2(aif0), vgo0 = unpack2(ago0);
            float2 vif1 = unpack2(aif1), vgo1 = unpack2(ago1);
            c0 = sigm(vif0.y) * c0 + sigm(vif0.x) * tanh_f(vgo0.x);
            c1 = sigm(vif1.y) * c1 + sigm(vif1.x) * tanh_f(vgo1.x);
            h0 = sigm(vgo0.y) * tanh_f(c0);
            h1 = sigm(vgo1.y) * tanh_f(c1);
            // DSMEM all-to-all: write (u, 2 seqs) dup-pairs into every rank's buffer (s&1)
            unsigned off = (unsigned)((s & 1) * 2048 * 8) + my_off;
            ull v0 = pack2(h0, h0), v1 = pack2(h1, h1);
            #pragma unroll
            for (int rk = 0; rk < 8; rk++) {
                unsigned a = rank_base[rk] + off;
                st_cluster_u64(a, v0);
                st_cluster_u64(a + 8, v1);
            }
        }
        asm volatile("barrier.cluster.arrive.aligned;" ::: "memory");
        if (!kq) {
            // off the cluster critical path: persist h for k_final + prefetch next biases
            *(float2*)(hout_base + (size_t)l * NHID * NB + urow * NB + bg0) = make_float2(h0, h1);
            if (s + 1 < L) {
                int ln = dir ? (L - 2 - s) : (s + 1);
                int tok0 = g_tok[bg0 * LMAX + ln];
                int tok1 = g_tok[(bg0 + 1) * LMAX + ln];
                const float* tr0 = tabd + tok0 * G4 + urow;
                const float* tr1 = tabd + tok1 * G4 + urow;
                pf_if0 = pack2(tr0[0], tr0[NHID]); pf_go0 = pack2(tr0[2 * NHID], tr0[3 * NHID]);
                pf_if1 = pack2(tr1[0], tr1[NHID]); pf_go1 = pack2(tr1[2 * NHID], tr1[3 * NHID]);
            }
        }
        asm volatile("barrier.cluster.wait.aligned;" ::: "memory");
    }
}

// ---------------- K4: final linear (concat(hf,hb) @ lin_w.T + lin_b) ----------------
#define WPAD  68
#define HSPAD 516
#define FIN_SMEM (16 * HSPAD * 4 + NMEL * WPAD * 4)

__global__ void __launch_bounds__(256)
k_final(const float* __restrict__ lin_w, const float* __restrict__ lin_b,
        float* __restrict__ out, int L) {
    extern __shared__ float sm[];
    float* hs = sm;               // [16][HSPAD]  cols 0..255 = hf, 256..511 = hb
    float* ws = sm + 16 * HSPAD;  // [80][WPAD]
    int l = blockIdx.x, b0 = blockIdx.y * 16;
    int tid = threadIdx.x;
    int bl   = tid >> 4;          // batch 0..15
    int mg   = tid & 15;          // mel group: mels mg*5 .. mg*5+4
    const float* hf = g_h + (size_t)l * NHID * NB + b0;                           // [u][b]
    const float* hb = g_h + (size_t)LMAX * NHID * NB + (size_t)l * NHID * NB + b0;
    for (int i = tid; i < 256 * 16; i += 256) {
        int u = i >> 4, bb = i & 15;              // b fastest -> coalesced 64B segments
        hs[bb * HSPAD + u]       = hf[u * NB + bb];
        hs[bb * HSPAD + 256 + u] = hb[u * NB + bb];
    }
    float acc[5] = {0, 0, 0, 0, 0};
    for (int kc = 0; kc < 512; kc += 64) {
        __syncthreads();
        for (int i = tid; i < NMEL * 64; i += 256) {
            int m = i >> 6, kk = i & 63;
            ws[m * WPAD + kk] = lin_w[m * 512 + kc + kk];
        }
        __syncthreads();
        const float* hrow = hs + bl * HSPAD + kc;
        #pragma unroll 4
        for (int kk = 0; kk < 64; kk += 4) {
            float4 hv = *(const float4*)(hrow + kk);      // one h vector, reused 5x
            #pragma unroll
            for (int j = 0; j < 5; j++) {
                float4 wv = *(const float4*)(ws + (mg * 5 + j) * WPAD + kk);
                acc[j] += hv.x * wv.x + hv.y * wv.y + hv.z * wv.z + hv.w * wv.w;
            }
        }
    }
    #pragma unroll
    for (int j = 0; j < 5; j++) {
        int m = mg * 5 + j;
        out[(size_t)(b0 + bl) * L * NMEL + (size_t)l * NMEL + m] = acc[j] + lin_b[m];
    }
}

// ---------------- launch ----------------
extern "C" void kernel_launch(void* const* d_in, const int* in_sizes, int n_in,
                              void* d_out, int out_size) {
    const int*   x      = (const int*)  d_in[0];
    const float* embed  = (const float*)d_in[1];
    const float* dp_w   = (const float*)d_in[2];
    const float* dp_b   = (const float*)d_in[3];
    const float* wih_f  = (const float*)d_in[4];
    const float* whh_f  = (const float*)d_in[5];
    const float* bih_f  = (const float*)d_in[6];
    const float* bhh_f  = (const float*)d_in[7];
    const float* wih_b  = (const float*)d_in[8];
    const float* whh_b  = (const float*)d_in[9];
    const float* bih_b  = (const float*)d_in[10];
    const float* bhh_b  = (const float*)d_in[11];
    const float* lin_w  = (const float*)d_in[12];
    const float* lin_b  = (const float*)d_in[13];
    float* out = (float*)d_out;

    int L = out_size / (NB * NMEL);
    if (L > LMAX) L = LMAX;
    if (L < 1)    L = 1;

    cudaFuncSetAttribute(k_lstm,  cudaFuncAttributeMaxDynamicSharedMemorySize, LSTM_SMEM);
    cudaFuncSetAttribute(k_final, cudaFuncAttributeMaxDynamicSharedMemorySize, FIN_SMEM);

    k_tab   <<<514, 256>>>(embed, wih_f, bih_f, bhh_f, wih_b, bih_b, bhh_b);
    k_expand<<<NB, NT>>>(x, embed, dp_w, dp_b, L);
    k_lstm  <<<128, 512, LSTM_SMEM>>>(whh_f, whh_b, L);
    k_final <<<dim3(L, 4), 256, FIN_SMEM>>>(lin_w, lin_b, out, L);
}